// round 11
// baseline (speedup 1.0000x reference)
#include <cuda_runtime.h>
#include <cstdint>

// p-bit Glauber sequential update, N=4096 spins, 16384 steps.
// prep_all: F0 = J@m0+h | per-window tables (W=64) Jw/Jc | thr=atanh(2u-1).
// pbit_dynamics: 2-CTA CLUSTER, 544 thr/CTA, mbarrier-only pipeline:
//   CTA r owners (512 thr) hold F elements [2048r, 2048r+2048) (float4/thread).
//   Per flip each CTA applies only its 8KB half-row -> per-SM L1 traffic halves.
//   CTA0 warp0 = evaluator: identical decision arithmetic to R10 (gather value
//   = bit-exact F at window indices, Jc catch-up of prev window's flips, Jw
//   in-window resolution). Owners mirror their slice in smem; a relay warp per
//   CTA DSMEM-pushes the <=64 gather floats for window p+1 to CTA0 (release-
//   arrive, count 64). Evaluator broadcasts flip lists to both CTAs (count 32).
//   Zero __syncthreads in the loop; owners use bar.sync 1,512 twice per window.

#define NN      4096
#define NSTEPS  16384
#define W       64
#define NWIN    (NSTEPS / W)      // 256
#define TPB     544
#define NOWN    512
#define HALF    2048
#define FULLM   0xffffffffu

__device__ float  g_F[NN];
__device__ float2 g_TI[NSTEPS];
__device__ float  g_Jw[NWIN * W * W];   // 4MB
__device__ float  g_Jc[NWIN * W * W];   // 4MB

struct Sm {
    float Jw[2][W * W];       // 32KB (CTA0)
    float Jc[2][W * W];       // 32KB (CTA0)
    float Fslice[HALF];       // 8KB  mirror of this CTA's F slice
    float gbuf[2][W];         // CTA0: gathered F at window indices
    int   flist[2][W];
    int   fcnt[2];
    signed char m[NN];        // CTA0 (evaluator-owned)
    unsigned long long gathMbar;   // CTA0, count 64
    unsigned long long flipMbar;   // per-CTA, count 32
};
#define SMEM_BYTES ((int)sizeof(Sm))

// ---------------------------------------------------------------------------
__device__ __forceinline__ uint32_t smem_u32(const void* p) {
    uint32_t a;
    asm("{ .reg .u64 t; cvta.to.shared.u64 t, %1; cvt.u32.u64 %0, t; }"
        : "=r"(a) : "l"(p));
    return a;
}
__device__ __forceinline__ uint32_t ctarank() {
    uint32_t r;
    asm("mov.u32 %0, %%cluster_ctarank;" : "=r"(r));
    return r;
}
__device__ __forceinline__ void mbar_init(uint32_t a, uint32_t cnt) {
    asm volatile("mbarrier.init.shared.b64 [%0], %1;" :: "r"(a), "r"(cnt) : "memory");
}
__device__ __forceinline__ void mbar_wait_cl(uint32_t a, uint32_t parity) {
    asm volatile(
        "{\n\t.reg .pred P;\n\t"
        "WLP_%=:\n\t"
        "mbarrier.try_wait.parity.acquire.cluster.shared::cta.b64 P, [%0], %1, 0x989680;\n\t"
        "@P bra.uni WDN_%=;\n\t"
        "bra.uni WLP_%=;\n\t"
        "WDN_%=:\n\t}"
        :: "r"(a), "r"(parity) : "memory");
}
__device__ __forceinline__ void mbar_arrive_cl(uint32_t local_addr, uint32_t rank) {
    asm volatile(
        "{\n\t.reg .b32 ra;\n\t"
        "mapa.shared::cluster.u32 ra, %0, %1;\n\t"
        "mbarrier.arrive.release.cluster.shared::cluster.b64 _, [ra];\n\t}"
        :: "r"(local_addr), "r"(rank) : "memory");
}
__device__ __forceinline__ void st_remote_f32(uint32_t local_addr, uint32_t rank, float v) {
    asm volatile(
        "{\n\t.reg .b32 ra;\n\t"
        "mapa.shared::cluster.u32 ra, %0, %1;\n\t"
        "st.shared::cluster.f32 [ra], %2;\n\t}"
        :: "r"(local_addr), "r"(rank), "f"(v) : "memory");
}
__device__ __forceinline__ void st_remote_i32(uint32_t local_addr, uint32_t rank, int v) {
    asm volatile(
        "{\n\t.reg .b32 ra;\n\t"
        "mapa.shared::cluster.u32 ra, %0, %1;\n\t"
        "st.shared::cluster.b32 [ra], %2;\n\t}"
        :: "r"(local_addr), "r"(rank), "r"(v) : "memory");
}

// ---------------------------------------------------------------------------
// fused prep: init_field rows | pack window tables | thresholds
// ---------------------------------------------------------------------------
__global__ void prep_all(const float* __restrict__ J,
                         const float* __restrict__ h,
                         const float* __restrict__ m0,
                         const int*   __restrict__ idx,
                         const float* __restrict__ u) {
    const int bid = blockIdx.x;
    if (bid < NN) {
        const int row = bid;
        const float4* __restrict__ Jr =
            reinterpret_cast<const float4*>(J) + (size_t)row * (NN / 4);
        const float4* __restrict__ M4 = reinterpret_cast<const float4*>(m0);
        float sum = 0.0f;
        for (int k = threadIdx.x; k < NN / 4; k += blockDim.x) {
            float4 a = Jr[k];
            float4 b = M4[k];
            sum += a.x * b.x + a.y * b.y + a.z * b.z + a.w * b.w;
        }
        #pragma unroll
        for (int off = 16; off; off >>= 1)
            sum += __shfl_xor_sync(FULLM, sum, off);
        __shared__ float ws[8];
        const int lane = threadIdx.x & 31;
        const int wid  = threadIdx.x >> 5;
        if (lane == 0) ws[wid] = sum;
        __syncthreads();
        if (threadIdx.x == 0) {
            float tot = 0.0f;
            #pragma unroll
            for (int w = 0; w < 8; w++) tot += ws[w];
            g_F[row] = tot + h[row];
        }
    } else if (bid < NN + NWIN) {
        const int w = bid - NN;
        for (int e = threadIdx.x; e < W * W; e += blockDim.x) {
            const int k = e >> 6;
            const int l = e & 63;
            const int il = idx[w * W + l];
            const int ik = idx[w * W + k];
            g_Jw[(size_t)w * W * W + e] = J[(size_t)ik * NN + il];
            float jc = 0.0f;
            if (w > 0) {
                const int ikp = idx[(w - 1) * W + k];
                jc = J[(size_t)ikp * NN + il];
            }
            g_Jc[(size_t)w * W * W + e] = jc;
        }
    } else {
        const int t = (bid - NN - NWIN) * blockDim.x + threadIdx.x;
        if (t < NSTEPS) {
            const float r = 2.0f * u[t] - 1.0f;
            g_TI[t] = make_float2(atanhf(r), __int_as_float(idx[t]));
        }
    }
}

// ---------------------------------------------------------------------------
__global__ __launch_bounds__(TPB, 1) __cluster_dims__(2, 1, 1)
void pbit_dynamics(const float* __restrict__ J,
                   const float* __restrict__ m0,
                   float*       __restrict__ out) {
    extern __shared__ char raw[];
    Sm* S = reinterpret_cast<Sm*>(raw);

    const int tid  = threadIdx.x;
    const int lane = tid & 31;
    const uint32_t rank = ctarank();
    const bool is_ev  = (rank == 0) && (tid < 32);
    const bool is_own = (tid >= 32);
    const bool is_rel = (tid >= 32 && tid < 64);
    const int oid = tid - 32;
    const int sliceBase = (int)rank * HALF;

    const uint32_t gmA = smem_u32(&S->gathMbar);
    const uint32_t fmA = smem_u32(&S->flipMbar);
    if (tid == 0) { mbar_init(fmA, 32); mbar_init(gmA, 64); }

    // owner F slice: one float4 per thread, bit-identical layout to R10's F
    float4 Fr = make_float4(0.f, 0.f, 0.f, 0.f);
    if (is_own) {
        Fr = reinterpret_cast<const float4*>(g_F)[rank * NOWN + oid];
        reinterpret_cast<float4*>(S->Fslice)[oid] = Fr;
    }
    if (rank == 0)
        for (int k = tid; k < NN; k += TPB)
            S->m[k] = (m0[k] > 0.0f) ? 1 : -1;
    if (rank == 0 && is_own) {                 // stage window 0 tables
        const float4* sw = reinterpret_cast<const float4*>(g_Jw);
        const float4* sc = reinterpret_cast<const float4*>(g_Jc);
        reinterpret_cast<float4*>(S->Jw[0])[oid]        = sw[oid];
        reinterpret_cast<float4*>(S->Jw[0])[oid + NOWN] = sw[oid + NOWN];
        reinterpret_cast<float4*>(S->Jc[0])[oid]        = sc[oid];
        reinterpret_cast<float4*>(S->Jc[0])[oid + NOWN] = sc[oid + NOWN];
    }
    __syncthreads();
    asm volatile("barrier.cluster.arrive.aligned;" ::: "memory");
    asm volatile("barrier.cluster.wait.aligned;" ::: "memory");

    // relay prologue: gather window 0 (state = F0), arrive phase 0
    int ix0 = 0, ix1 = 0;
    if (is_rel) {
        ix0 = __float_as_int(g_TI[lane].y);
        ix1 = __float_as_int(g_TI[32 + lane].y);
        if ((unsigned)(ix0 - sliceBase) < (unsigned)HALF)
            st_remote_f32(smem_u32(&S->gbuf[0][lane]), 0, S->Fslice[ix0 - sliceBase]);
        if ((unsigned)(ix1 - sliceBase) < (unsigned)HALF)
            st_remote_f32(smem_u32(&S->gbuf[0][32 + lane]), 0, S->Fslice[ix1 - sliceBase]);
        mbar_arrive_cl(gmA, 0);
        ix0 = __float_as_int(g_TI[W + lane].y);       // window 1 indices
        ix1 = __float_as_int(g_TI[W + 32 + lane].y);
    }

    if (is_ev) {
        // ======================= evaluator (CTA0 warp 0) =======================
        float2 tiPF0 = g_TI[lane];
        float2 tiPF1 = g_TI[32 + lane];
        unsigned prevM0 = 0, prevS0 = 0, prevM1 = 0, prevS1 = 0;

        for (int p = 0; p < NWIN; p++) {
            const int par = p & 1;
            mbar_wait_cl(gmA, par);                 // gbuf(p) ready (state p-2)
            float f0  = S->gbuf[par][lane];
            float f1v = S->gbuf[par][32 + lane];
            const float thr0 = tiPF0.x;
            const int   i0   = __float_as_int(tiPF0.y);
            const float thr1 = tiPF1.x;
            const int   i1x  = __float_as_int(tiPF1.y);
            bool pos0 = (S->m[i0]  > 0);
            bool pos1 = (S->m[i1x] > 0);
            if (p + 1 < NWIN) {
                tiPF0 = g_TI[(p + 1) * W + lane];
                tiPF1 = g_TI[(p + 1) * W + 32 + lane];
            }

            // catch up window p-1's flips (chronological == owner order)
            const float* JcP = S->Jc[par];
            {
                unsigned mm = prevM0;
                while (mm) {
                    const int k = __ffs(mm) - 1;
                    mm &= mm - 1;
                    const float dk = ((prevS0 >> k) & 1u) ? 2.0f : -2.0f;
                    f0  = fmaf(JcP[(k << 6) + lane],      dk, f0);
                    f1v = fmaf(JcP[(k << 6) + 32 + lane], dk, f1v);
                }
                mm = prevM1;
                while (mm) {
                    const int k = __ffs(mm) - 1;
                    mm &= mm - 1;
                    const int r = 32 + k;
                    const float dk = ((prevS1 >> k) & 1u) ? 2.0f : -2.0f;
                    f0  = fmaf(JcP[(r << 6) + lane],      dk, f0);
                    f1v = fmaf(JcP[(r << 6) + 32 + lane], dk, f1v);
                }
            }

            const float* JwP = S->Jw[par];
            unsigned nM0 = 0, nS0 = 0, nM1 = 0, nS1 = 0;
            int cnt = 0;

            // ---- half A: steps 0..31 ----
            {
                bool sp = (f0 >= thr0);
                bool fl = sp != pos0;
                unsigned fb  = __ballot_sync(FULLM, fl);
                unsigned sbm = __ballot_sync(FULLM, sp);
                while (fb) {
                    const int  f = __ffs(fb) - 1;
                    const bool s1 = (sbm >> f) & 1u;
                    const float d = s1 ? 2.0f : -2.0f;
                    const float jva = JwP[(f << 6) + lane];
                    const float jvb = JwP[(f << 6) + 32 + lane];
                    const int   ii  = __shfl_sync(FULLM, i0, f);
                    if (lane == f) {
                        S->m[ii] = s1 ? 1 : -1;
                        S->flist[par][cnt] = ii | (s1 ? (1 << 30) : 0);
                    }
                    nM0 |= 1u << f;
                    if (s1) nS0 |= 1u << f;
                    cnt++;
                    f0  = fmaf(jva, d, f0);
                    f1v = fmaf(jvb, d, f1v);
                    if (i0  == ii) pos0 = s1;
                    if (i1x == ii) pos1 = s1;
                    bool ns = false, nf2 = false;
                    if (lane > f) {
                        ns  = (f0 >= thr0);
                        nf2 = ns != pos0;
                    }
                    fb  = __ballot_sync(FULLM, nf2);
                    sbm = __ballot_sync(FULLM, ns);
                }
            }
            // ---- half B: steps 32..63 ----
            {
                bool sp = (f1v >= thr1);
                bool fl = sp != pos1;
                unsigned fb  = __ballot_sync(FULLM, fl);
                unsigned sbm = __ballot_sync(FULLM, sp);
                while (fb) {
                    const int  f = __ffs(fb) - 1;
                    const bool s1 = (sbm >> f) & 1u;
                    const float d = s1 ? 2.0f : -2.0f;
                    const int  r = 32 + f;
                    const float jvb = JwP[(r << 6) + 32 + lane];
                    const int   ii  = __shfl_sync(FULLM, i1x, f);
                    if (lane == f) {
                        S->m[ii] = s1 ? 1 : -1;
                        S->flist[par][cnt] = ii | (s1 ? (1 << 30) : 0);
                    }
                    nM1 |= 1u << f;
                    if (s1) nS1 |= 1u << f;
                    cnt++;
                    f1v = fmaf(jvb, d, f1v);
                    if (i1x == ii) pos1 = s1;
                    bool ns = false, nf2 = false;
                    if (lane > f) {
                        ns  = (f1v >= thr1);
                        nf2 = ns != pos1;
                    }
                    fb  = __ballot_sync(FULLM, nf2);
                    sbm = __ballot_sync(FULLM, ns);
                }
            }
            if (lane == 0) S->fcnt[par] = cnt;
            __syncwarp();
            if (p + 1 < NWIN) {
                // broadcast flip list to CTA1, then release both flip barriers
                if (lane < cnt)
                    st_remote_i32(smem_u32(&S->flist[par][lane]), 1, S->flist[par][lane]);
                if (lane + 32 < cnt)
                    st_remote_i32(smem_u32(&S->flist[par][lane + 32]), 1,
                                  S->flist[par][lane + 32]);
                if (lane == 0)
                    st_remote_i32(smem_u32(&S->fcnt[par]), 1, cnt);
                mbar_arrive_cl(fmA, 0);
                mbar_arrive_cl(fmA, 1);
            }
            prevM0 = nM0; prevS0 = nS0;
            prevM1 = nM1; prevS1 = nS1;
        }
    } else if (is_own) {
        // ======================= owners (both CTAs) =======================
        for (int p = 0; p < NWIN; p++) {
            const int par = p & 1;

            // staging loads (CTA0, flip-independent -> before the wait)
            float4 sw0, sw1, sc0, sc1;
            const bool hasStage = (rank == 0) && (p + 1 < NWIN);
            if (hasStage) {
                const float4* sw =
                    reinterpret_cast<const float4*>(g_Jw + (size_t)(p + 1) * (W * W));
                const float4* sc =
                    reinterpret_cast<const float4*>(g_Jc + (size_t)(p + 1) * (W * W));
                sw0 = sw[oid]; sw1 = sw[oid + NOWN];
                sc0 = sc[oid]; sc1 = sc[oid + NOWN];
            }

            int np = 0;
            if (p > 0) {
                mbar_wait_cl(fmA, (p - 1) & 1);
                np = S->fcnt[(p - 1) & 1];
            }
            const int* fl = S->flist[(p - 1) & 1];

            // apply window p-1's flips to this CTA's half-row slice (8KB/flip)
            for (int kb = 0; kb < np; kb += 4) {
                float  dd[4];
                float4 v[4];
                #pragma unroll
                for (int j = 0; j < 4; j++) {
                    const bool vld = (kb + j < np);
                    const int e = vld ? fl[kb + j] : 0;
                    dd[j] = vld ? ((e & (1 << 30)) ? 2.0f : -2.0f) : 0.0f;
                    const int ik = e & 0xFFFF;
                    v[j] = vld
                        ? reinterpret_cast<const float4*>(J + (size_t)ik * NN)[rank * NOWN + oid]
                        : make_float4(0.f, 0.f, 0.f, 0.f);
                }
                #pragma unroll
                for (int j = 0; j < 4; j++) {
                    Fr.x = fmaf(v[j].x, dd[j], Fr.x);
                    Fr.y = fmaf(v[j].y, dd[j], Fr.y);
                    Fr.z = fmaf(v[j].z, dd[j], Fr.z);
                    Fr.w = fmaf(v[j].w, dd[j], Fr.w);
                }
            }
            if (np > 0)
                reinterpret_cast<float4*>(S->Fslice)[oid] = Fr;
            if (hasStage) {
                reinterpret_cast<float4*>(S->Jw[par ^ 1])[oid]        = sw0;
                reinterpret_cast<float4*>(S->Jw[par ^ 1])[oid + NOWN] = sw1;
                reinterpret_cast<float4*>(S->Jc[par ^ 1])[oid]        = sc0;
                reinterpret_cast<float4*>(S->Jc[par ^ 1])[oid + NOWN] = sc1;
            }
            asm volatile("bar.sync 1, 512;" ::: "memory");   // STS drained

            if (is_rel && p + 1 < NWIN) {
                // push gather values for window p+1 (state p-1) to CTA0
                if ((unsigned)(ix0 - sliceBase) < (unsigned)HALF)
                    st_remote_f32(smem_u32(&S->gbuf[par ^ 1][lane]), 0,
                                  S->Fslice[ix0 - sliceBase]);
                if ((unsigned)(ix1 - sliceBase) < (unsigned)HALF)
                    st_remote_f32(smem_u32(&S->gbuf[par ^ 1][32 + lane]), 0,
                                  S->Fslice[ix1 - sliceBase]);
                mbar_arrive_cl(gmA, 0);
                if (p + 2 < NWIN) {
                    ix0 = __float_as_int(g_TI[(p + 2) * W + lane].y);
                    ix1 = __float_as_int(g_TI[(p + 2) * W + 32 + lane].y);
                }
            }
            asm volatile("bar.sync 1, 512;" ::: "memory");   // relay LDS done
        }
    }

    __syncthreads();
    asm volatile("barrier.cluster.arrive.aligned;" ::: "memory");
    asm volatile("barrier.cluster.wait.aligned;" ::: "memory");
    if (rank == 0)
        for (int k = tid; k < NN; k += TPB)
            out[k] = (float)S->m[k];
}

// ---------------------------------------------------------------------------
extern "C" void kernel_launch(void* const* d_in, const int* in_sizes, int n_in,
                              void* d_out, int out_size) {
    const float* J  = (const float*)d_in[0];
    const float* h  = (const float*)d_in[1];
    const float* m0 = (const float*)d_in[2];
    const int*   idx= (const int*)  d_in[3];
    const float* u  = (const float*)d_in[4];
    float* out = (float*)d_out;

    static bool attrSet = false;
    if (!attrSet) {
        cudaFuncSetAttribute(pbit_dynamics,
                             cudaFuncAttributeMaxDynamicSharedMemorySize,
                             SMEM_BYTES);
        attrSet = true;
    }

    const int prepBlocks = NN + NWIN + (NSTEPS + 255) / 256;
    prep_all<<<prepBlocks, 256>>>(J, h, m0, idx, u);
    pbit_dynamics<<<2, TPB, SMEM_BYTES>>>(J, m0, out);
}